// round 3
// baseline (speedup 1.0000x reference)
#include <cuda_runtime.h>
#include <math_constants.h>
#include <cstdint>
#include <cstdio>

#define NSRC  10000
#define NEDGE 320000
#define DIM   128
#define EDIM  236
#define TOPN  6
#define NCAND_BLOCKS 250   // 250 * 1280 == 320000 exactly

// ----------------------------------------------------------------------------
// Scratch (device globals; no dynamic allocation allowed)
// ----------------------------------------------------------------------------
__device__ int   g_counts[NSRC];
__device__ int   g_cursor[NSRC];
__device__ int   g_offsets[NSRC];
__device__ int   g_edge_list[NEDGE];
__device__ float g_agg[NSRC * EDIM];
__device__ float g_H[NSRC * 3 * DIM];     // h_i = paths_srcs + agg@edgeW_i + b_i (concat)
__device__ float g_y[NSRC * DIM];
__device__ float g_z[NSRC * DIM];
__device__ float g_H2[NSRC * 3 * DIM];    // hs concat
__device__ float g_u[NSRC * DIM];
__device__ float g_ns[NSRC * DIM];        // node_emb @ pe_src_W
__device__ float g_SQ[2 * 3 * DIM];       // [S(3*128) | Q(3*128)] node BN stats
__device__ float g_ESQ[2 * DIM];          // edge BN stats
__device__ float g_alpha[DIM];
__device__ float g_beta[DIM];
__device__ float g_bias_pe[DIM];
__device__ float g_he[(size_t)NEDGE * DIM]; // per-edge pre-BN hpath (164 MB)
__device__ float g_scores[NEDGE];
__device__ float g_cvals[NCAND_BLOCKS * TOPN];
__device__ int   g_cidx[NCAND_BLOCKS * TOPN];

// ----------------------------------------------------------------------------
// CSR build
// ----------------------------------------------------------------------------
__global__ void count_kernel(const int* __restrict__ src) {
    int e = blockIdx.x * blockDim.x + threadIdx.x;
    if (e < NEDGE) atomicAdd(&g_counts[src[e]], 1);
}

__global__ void scan_kernel() {
    __shared__ int sh[1024];
    const int CH = 10;   // 1024*10 >= 10000
    int tid = threadIdx.x;
    int base = tid * CH;
    int loc[CH];
    int s = 0;
    #pragma unroll
    for (int j = 0; j < CH; j++) {
        int idx = base + j;
        int v = (idx < NSRC) ? g_counts[idx] : 0;
        loc[j] = s;
        s += v;
    }
    sh[tid] = s;
    __syncthreads();
    for (int off = 1; off < 1024; off <<= 1) {
        int v = (tid >= off) ? sh[tid - off] : 0;
        __syncthreads();
        sh[tid] += v;
        __syncthreads();
    }
    int pre = (tid == 0) ? 0 : sh[tid - 1];
    #pragma unroll
    for (int j = 0; j < CH; j++) {
        int idx = base + j;
        if (idx < NSRC) g_offsets[idx] = pre + loc[j];
    }
}

__global__ void scatter_kernel(const int* __restrict__ src) {
    int e = blockIdx.x * blockDim.x + threadIdx.x;
    if (e < NEDGE) {
        int s = src[e];
        int p = g_offsets[s] + atomicAdd(&g_cursor[s], 1);
        g_edge_list[p] = e;
    }
}

// Per-source aggregation: agg[s] = sum over edges of relu(path_feats[e])
__global__ void agg_kernel(const float* __restrict__ path_feats) {
    int s = blockIdx.x;
    int beg = g_offsets[s];
    int cnt = g_counts[s];
    int c0 = threadIdx.x;      // 0..127
    int c1 = c0 + DIM;         // may be >= EDIM
    float a0 = 0.f, a1 = 0.f;
    for (int i = 0; i < cnt; i++) {
        const float* row = path_feats + (size_t)g_edge_list[beg + i] * EDIM;
        a0 += fmaxf(row[c0], 0.f);
        if (c1 < EDIM) a1 += fmaxf(row[c1], 0.f);
    }
    g_agg[(size_t)s * EDIM + c0] = a0;
    if (c1 < EDIM) g_agg[(size_t)s * EDIM + c1] = a1;
}

// ----------------------------------------------------------------------------
// Generic tiled SGEMM, N fixed = 128, B row-major [K,128]
// epilogue: C = acc (+ bias[n]) (+ addmat[(gather?src:m)][n]) (relu?)
// ----------------------------------------------------------------------------
template <int BM, int TM>
__global__ __launch_bounds__(256)
void sgemm_k(const float* __restrict__ A, int lda,
             const float* __restrict__ B,
             float* __restrict__ C, int ldc,
             int M, int K,
             const float* __restrict__ bias,
             const float* __restrict__ addmat, int ld_add,
             const int* __restrict__ gather_idx,
             int do_relu)
{
    constexpr int BN = 128, BK = 16, TN = 8;
    __shared__ float As[BK][BM];
    __shared__ float Bs[BK][BN];

    int m0 = blockIdx.x * BM;
    int tid = threadIdx.x;
    int trow = tid / 16;   // 0..15
    int tcol = tid % 16;   // 0..15

    float acc[TM][TN];
    #pragma unroll
    for (int i = 0; i < TM; i++)
        #pragma unroll
        for (int j = 0; j < TN; j++) acc[i][j] = 0.f;

    int ntiles = (K + BK - 1) / BK;
    for (int t = 0; t < ntiles; t++) {
        int k0 = t * BK;
        // load A tile (BM x BK) -> As[k][m]
        constexpr int A4 = (BM * BK / 4) / 256;   // float4s per thread
        #pragma unroll
        for (int r = 0; r < A4; r++) {
            int idx = tid + r * 256;
            int m = idx / 4;
            int kq = (idx % 4) * 4;
            float4 v = make_float4(0.f, 0.f, 0.f, 0.f);
            int gm = m0 + m;
            if (gm < M) {
                int k = k0 + kq;
                if (k + 3 < K) {
                    v = *(const float4*)(A + (size_t)gm * lda + k);
                } else {
                    float tmp[4] = {0.f, 0.f, 0.f, 0.f};
                    #pragma unroll
                    for (int q = 0; q < 4; q++)
                        if (k + q < K) tmp[q] = A[(size_t)gm * lda + k + q];
                    v = make_float4(tmp[0], tmp[1], tmp[2], tmp[3]);
                }
            }
            As[kq + 0][m] = v.x;
            As[kq + 1][m] = v.y;
            As[kq + 2][m] = v.z;
            As[kq + 3][m] = v.w;
        }
        // load B tile (BK x 128)
        #pragma unroll
        for (int r = 0; r < 2; r++) {
            int idx = tid + r * 256;
            int k = idx / 32;
            int n = (idx % 32) * 4;
            float4 v = make_float4(0.f, 0.f, 0.f, 0.f);
            if (k0 + k < K) v = *(const float4*)(B + (size_t)(k0 + k) * BN + n);
            *(float4*)&Bs[k][n] = v;
        }
        __syncthreads();

        #pragma unroll
        for (int kk = 0; kk < BK; kk++) {
            float a[TM], b[TN];
            #pragma unroll
            for (int i = 0; i < TM; i++) a[i] = As[kk][trow * TM + i];
            #pragma unroll
            for (int j = 0; j < TN; j++) b[j] = Bs[kk][tcol * TN + j];
            #pragma unroll
            for (int i = 0; i < TM; i++)
                #pragma unroll
                for (int j = 0; j < TN; j++)
                    acc[i][j] = fmaf(a[i], b[j], acc[i][j]);
        }
        __syncthreads();
    }

    // epilogue
    #pragma unroll
    for (int i = 0; i < TM; i++) {
        int gm = m0 + trow * TM + i;
        if (gm >= M) continue;
        int arow = gather_idx ? gather_idx[gm] : gm;
        #pragma unroll
        for (int j = 0; j < TN; j++) {
            int gn = tcol * TN + j;
            float v = acc[i][j];
            if (bias)   v += bias[gn];
            if (addmat) v += addmat[(size_t)arow * ld_add + gn];
            if (do_relu) v = fmaxf(v, 0.f);
            C[(size_t)gm * ldc + gn] = v;
        }
    }
}

// ----------------------------------------------------------------------------
// Column stats (sum, sumsq) of an [M x 128] matrix
// ----------------------------------------------------------------------------
__global__ void colstats_kernel(const float* __restrict__ X, int M,
                                float* __restrict__ S, float* __restrict__ Q)
{
    int c = threadIdx.x;  // 128 threads
    float s = 0.f, q = 0.f;
    for (int r = blockIdx.x; r < M; r += gridDim.x) {
        float v = X[(size_t)r * DIM + c];
        s += v;
        q += v * v;
    }
    atomicAdd(&S[c], s);
    atomicAdd(&Q[c], q);
}

// z = relu(BN(y)) elementwise with batch stats
__global__ void bnrelu_kernel(const float* __restrict__ X, float* __restrict__ Z,
                              const float* __restrict__ S, const float* __restrict__ Q,
                              const float* __restrict__ g, const float* __restrict__ b,
                              int total, float invM)
{
    int i = blockIdx.x * blockDim.x + threadIdx.x;
    if (i >= total) return;
    int c = i & (DIM - 1);
    float mean = S[c] * invM;
    float var = Q[c] * invM - mean * mean;
    float v = (X[i] - mean) * rsqrtf(var + 1e-5f) * g[c] + b[c];
    Z[i] = fmaxf(v, 0.f);
}

__global__ void combine_bias_kernel(const float* __restrict__ b1,
                                    const float* __restrict__ b2)
{
    int c = threadIdx.x;
    g_bias_pe[c] = b1[c] + b2[c];
}

__global__ void edge_params_kernel(const float* __restrict__ g,
                                   const float* __restrict__ b)
{
    int c = threadIdx.x;
    const float invE = 1.0f / (float)NEDGE;
    float mean = g_ESQ[c] * invE;
    float var = g_ESQ[DIM + c] * invE - mean * mean;
    float a = g[c] * rsqrtf(var + 1e-5f);
    g_alpha[c] = a;
    g_beta[c] = b[c] - mean * a;
}

// scores[e] = sum_j relu(alpha_j*h[e][j] + beta_j) * w_j   (warp per edge)
__global__ void score_kernel(const float* __restrict__ w)
{
    __shared__ float sa[DIM], sb[DIM], sw[DIM];
    int tid = threadIdx.x;
    if (tid < DIM) { sa[tid] = g_alpha[tid]; sb[tid] = g_beta[tid]; sw[tid] = w[tid]; }
    __syncthreads();
    int warp = tid >> 5, lane = tid & 31;
    int nw = blockDim.x >> 5;
    for (int e = blockIdx.x * nw + warp; e < NEDGE; e += gridDim.x * nw) {
        const float* row = g_he + (size_t)e * DIM;
        float s = 0.f;
        #pragma unroll
        for (int j0 = 0; j0 < DIM; j0 += 32) {
            int j = j0 + lane;
            s += fmaxf(fmaf(sa[j], row[j], sb[j]), 0.f) * sw[j];
        }
        #pragma unroll
        for (int o = 16; o; o >>= 1) s += __shfl_down_sync(0xffffffffu, s, o);
        if (lane == 0) g_scores[e] = s;
    }
}

// ----------------------------------------------------------------------------
// Top-6: stage 1 = per-block top-6 of a 1280 chunk; stage 2 = final over cands
// ----------------------------------------------------------------------------
__global__ void topk_block_kernel()
{
    const int CHUNK = 1280;
    __shared__ float sv[CHUNK];
    __shared__ float rv[256];
    __shared__ int   ri[256];
    int tid = threadIdx.x;
    int base = blockIdx.x * CHUNK;
    for (int i = tid; i < CHUNK; i += 256) sv[i] = g_scores[base + i];
    __syncthreads();
    for (int r = 0; r < TOPN; r++) {
        float best = -CUDART_INF_F;
        int bi = 0x7fffffff;
        for (int i = tid; i < CHUNK; i += 256) {
            float v = sv[i];
            int gi = base + i;
            if (v > best || (v == best && gi < bi)) { best = v; bi = gi; }
        }
        rv[tid] = best; ri[tid] = bi;
        __syncthreads();
        for (int off = 128; off; off >>= 1) {
            if (tid < off) {
                float v2 = rv[tid + off]; int i2 = ri[tid + off];
                if (v2 > rv[tid] || (v2 == rv[tid] && i2 < ri[tid])) { rv[tid] = v2; ri[tid] = i2; }
            }
            __syncthreads();
        }
        if (tid == 0) {
            g_cvals[blockIdx.x * TOPN + r] = rv[0];
            g_cidx[blockIdx.x * TOPN + r] = ri[0];
            sv[ri[0] - base] = -CUDART_INF_F;   // mask winner
        }
        __syncthreads();
    }
}

__global__ void topk_final_kernel(float* __restrict__ out)
{
    const int NC = NCAND_BLOCKS * TOPN;   // 1500
    __shared__ float sv[NC];
    __shared__ int   si[NC];
    __shared__ float rv[256];
    __shared__ int   ri[256];
    int tid = threadIdx.x;
    for (int i = tid; i < NC; i += 256) { sv[i] = g_cvals[i]; si[i] = g_cidx[i]; }
    __syncthreads();
    for (int r = 0; r < TOPN; r++) {
        float best = -CUDART_INF_F;
        int bi = 0x7fffffff;
        int bslot = -1;
        for (int i = tid; i < NC; i += 256) {
            float v = sv[i];
            int gi = si[i];
            if (v > best || (v == best && gi < bi)) { best = v; bi = gi; bslot = i; }
        }
        rv[tid] = best; ri[tid] = (bslot << 0);
        // pack: keep slot via separate shared, easier to just redo compare with idx
        __syncthreads();
        // reduce on (value, global idx); track slot by re-find at end
        __shared__ int rslot[256];
        rslot[tid] = bslot;
        __shared__ int rgi[256];
        rgi[tid] = bi;
        __syncthreads();
        for (int off = 128; off; off >>= 1) {
            if (tid < off) {
                float v2 = rv[tid + off]; int i2 = rgi[tid + off]; int s2 = rslot[tid + off];
                if (v2 > rv[tid] || (v2 == rv[tid] && i2 < rgi[tid])) {
                    rv[tid] = v2; rgi[tid] = i2; rslot[tid] = s2;
                }
            }
            __syncthreads();
        }
        if (tid == 0) {
            out[(size_t)NSRC * DIM + r] = rv[0];
            out[(size_t)NSRC * DIM + TOPN + r] = (float)rgi[0];
            if (rslot[0] >= 0) sv[rslot[0]] = -CUDART_INF_F;
        }
        __syncthreads();
    }
}

// ----------------------------------------------------------------------------
// Launch
// ----------------------------------------------------------------------------
extern "C" void kernel_launch(void* const* d_in, const int* in_sizes, int n_in,
                              void* d_out, int out_size)
{
    (void)in_sizes; (void)n_in; (void)out_size;
    const float* paths_srcs  = (const float*)d_in[0];
    const float* path_feats  = (const float*)d_in[1];
    const int*   src_ids     = (const int*)  d_in[2];
    const float* conv_edge_W = (const float*)d_in[3];
    const float* conv_edge_b = (const float*)d_in[4];
    const float* conv_W1     = (const float*)d_in[5];
    const float* conv_bn_g   = (const float*)d_in[6];
    const float* conv_bn_b   = (const float*)d_in[7];
    const float* conv_W2     = (const float*)d_in[8];
    const float* lin1_W      = (const float*)d_in[9];
    const float* lin1_b      = (const float*)d_in[10];
    const float* lin2_W      = (const float*)d_in[11];
    const float* lin2_b      = (const float*)d_in[12];
    const float* pe_src_W    = (const float*)d_in[13];
    const float* pe_src_b    = (const float*)d_in[14];
    const float* pe_tgt_W    = (const float*)d_in[15];
    const float* pe_tgt_b    = (const float*)d_in[16];
    const float* pe_bn_g     = (const float*)d_in[17];
    const float* pe_bn_b     = (const float*)d_in[18];
    const float* score_w     = (const float*)d_in[19];
    float* out = (float*)d_out;

    // scratch addresses
    void *p_counts, *p_cursor, *p_SQ, *p_ESQ;
    cudaGetSymbolAddress(&p_counts, g_counts);
    cudaGetSymbolAddress(&p_cursor, g_cursor);
    cudaGetSymbolAddress(&p_SQ, g_SQ);
    cudaGetSymbolAddress(&p_ESQ, g_ESQ);
    float *agg, *H, *y, *z, *H2, *u, *ns, *he, *bias_pe;
    cudaGetSymbolAddress((void**)&agg, g_agg);
    cudaGetSymbolAddress((void**)&H, g_H);
    cudaGetSymbolAddress((void**)&y, g_y);
    cudaGetSymbolAddress((void**)&z, g_z);
    cudaGetSymbolAddress((void**)&H2, g_H2);
    cudaGetSymbolAddress((void**)&u, g_u);
    cudaGetSymbolAddress((void**)&ns, g_ns);
    cudaGetSymbolAddress((void**)&he, g_he);
    cudaGetSymbolAddress((void**)&bias_pe, g_bias_pe);
    float* S = (float*)p_SQ;
    float* Q = S + 3 * DIM;
    float* ES = (float*)p_ESQ;
    float* EQ = ES + DIM;

    cudaMemsetAsync(p_counts, 0, NSRC * sizeof(int));
    cudaMemsetAsync(p_cursor, 0, NSRC * sizeof(int));
    cudaMemsetAsync(p_SQ, 0, 2 * 3 * DIM * sizeof(float));
    cudaMemsetAsync(p_ESQ, 0, 2 * DIM * sizeof(float));

    // CSR build + aggregation
    count_kernel<<<(NEDGE + 255) / 256, 256>>>(src_ids);
    scan_kernel<<<1, 1024>>>();
    scatter_kernel<<<(NEDGE + 255) / 256, 256>>>(src_ids);
    agg_kernel<<<NSRC, DIM>>>(path_feats);

    const int NODE_GRID = (NSRC + 63) / 64;   // 157

    // h_i = paths_srcs + agg @ edgeW_i + b_i  (into H columns [i*128, i*128+128))
    for (int i = 0; i < 3; i++) {
        sgemm_k<64, 4><<<NODE_GRID, 256>>>(
            agg, EDIM, conv_edge_W + (size_t)i * EDIM * DIM,
            H + i * DIM, 3 * DIM, NSRC, EDIM,
            conv_edge_b + i * DIM, paths_srcs, DIM, nullptr, 0);
    }
    // per conv: y = h_i @ W1_i ; stats ; z = relu(BN(y)) ; hs_i = z @ W2_i
    for (int i = 0; i < 3; i++) {
        sgemm_k<64, 4><<<NODE_GRID, 256>>>(
            H + i * DIM, 3 * DIM, conv_W1 + (size_t)i * DIM * DIM,
            y, DIM, NSRC, DIM, nullptr, nullptr, 0, nullptr, 0);
        colstats_kernel<<<256, DIM>>>(y, NSRC, S + i * DIM, Q + i * DIM);
        bnrelu_kernel<<<(NSRC * DIM + 255) / 256, 256>>>(
            y, z, S + i * DIM, Q + i * DIM,
            conv_bn_g + i * DIM, conv_bn_b + i * DIM, NSRC * DIM, 1.0f / NSRC);
        sgemm_k<64, 4><<<NODE_GRID, 256>>>(
            z, DIM, conv_W2 + (size_t)i * DIM * DIM,
            H2 + i * DIM, 3 * DIM, NSRC, DIM, nullptr, nullptr, 0, nullptr, 0);
    }
    // u = relu(H2 @ lin1 + b1) ; node_emb = u @ lin2 + b2 (directly into d_out)
    sgemm_k<64, 4><<<NODE_GRID, 256>>>(
        H2, 3 * DIM, lin1_W, u, DIM, NSRC, 3 * DIM, lin1_b, nullptr, 0, nullptr, 1);
    sgemm_k<64, 4><<<NODE_GRID, 256>>>(
        u, DIM, lin2_W, out, DIM, NSRC, DIM, lin2_b, nullptr, 0, nullptr, 0);
    // ns = node_emb @ pe_src_W (bias folded into edge epilogue)
    sgemm_k<64, 4><<<NODE_GRID, 256>>>(
        out, DIM, pe_src_W, ns, DIM, NSRC, DIM, nullptr, nullptr, 0, nullptr, 0);

    // edge phase: h_e = path_feats @ pe_tgt_W + ns[src_e] + (pe_src_b + pe_tgt_b)
    combine_bias_kernel<<<1, DIM>>>(pe_src_b, pe_tgt_b);
    sgemm_k<128, 8><<<(NEDGE + 127) / 128, 256>>>(
        path_feats, EDIM, pe_tgt_W, he, DIM, NEDGE, EDIM,
        bias_pe, ns, DIM, src_ids, 0);

    // edge BN stats -> params -> scores -> top-6
    colstats_kernel<<<2048, DIM>>>(he, NEDGE, ES, EQ);
    edge_params_kernel<<<1, DIM>>>(pe_bn_g, pe_bn_b);
    score_kernel<<<512, 256>>>(score_w);
    topk_block_kernel<<<NCAND_BLOCKS, 256>>>();
    topk_final_kernel<<<1, 256>>>(out);
}

// round 4
// speedup vs baseline: 1.4247x; 1.4247x over previous
#include <cuda_runtime.h>
#include <math_constants.h>
#include <cstdint>
#include <cstdio>

#define NSRC  10000
#define NEDGE 320000
#define DIM   128
#define EDIM  236
#define TOPN  6
#define NCAND_BLOCKS 250   // 250 * 1280 == 320000 exactly

// ----------------------------------------------------------------------------
// Scratch (device globals; no dynamic allocation allowed)
// ----------------------------------------------------------------------------
__device__ int   g_counts[NSRC];
__device__ int   g_cursor[NSRC];
__device__ int   g_offsets[NSRC];
__device__ int   g_edge_list[NEDGE];
__device__ float g_agg[NSRC * EDIM];
__device__ float g_H[NSRC * 3 * DIM];     // h_i concat
__device__ float g_y[3 * NSRC * DIM];
__device__ float g_z[3 * NSRC * DIM];
__device__ float g_H2[NSRC * 3 * DIM];    // hs concat
__device__ float g_u[NSRC * DIM];
__device__ float g_ns[NSRC * DIM];        // node_emb @ pe_src_W
__device__ float g_SQ[2 * 3 * DIM];       // [S(3*128) | Q(3*128)] node BN stats
__device__ float g_ESQ[2 * DIM];          // edge BN stats
__device__ float g_alpha[DIM];
__device__ float g_beta[DIM];
__device__ float g_bias_pe[DIM];
__device__ float g_he[(size_t)NEDGE * DIM]; // per-edge pre-BN hpath (164 MB)
__device__ float g_scores[NEDGE];
__device__ float g_cvals[NCAND_BLOCKS * TOPN];
__device__ int   g_cidx[NCAND_BLOCKS * TOPN];

// ----------------------------------------------------------------------------
// CSR build
// ----------------------------------------------------------------------------
__global__ void count_kernel(const int* __restrict__ src) {
    int e = blockIdx.x * blockDim.x + threadIdx.x;
    if (e < NEDGE) atomicAdd(&g_counts[src[e]], 1);
}

__global__ void scan_kernel() {
    __shared__ int sh[1024];
    const int CH = 10;
    int tid = threadIdx.x;
    int base = tid * CH;
    int loc[CH];
    int s = 0;
    #pragma unroll
    for (int j = 0; j < CH; j++) {
        int idx = base + j;
        int v = (idx < NSRC) ? g_counts[idx] : 0;
        loc[j] = s;
        s += v;
    }
    sh[tid] = s;
    __syncthreads();
    for (int off = 1; off < 1024; off <<= 1) {
        int v = (tid >= off) ? sh[tid - off] : 0;
        __syncthreads();
        sh[tid] += v;
        __syncthreads();
    }
    int pre = (tid == 0) ? 0 : sh[tid - 1];
    #pragma unroll
    for (int j = 0; j < CH; j++) {
        int idx = base + j;
        if (idx < NSRC) g_offsets[idx] = pre + loc[j];
    }
}

__global__ void scatter_kernel(const int* __restrict__ src) {
    int e = blockIdx.x * blockDim.x + threadIdx.x;
    if (e < NEDGE) {
        int s = src[e];
        int p = g_offsets[s] + atomicAdd(&g_cursor[s], 1);
        g_edge_list[p] = e;
    }
}

// Per-source aggregation: agg[s] = sum over edges of relu(path_feats[e])
__global__ void agg_kernel(const float* __restrict__ path_feats) {
    int s = blockIdx.x;
    int beg = g_offsets[s];
    int cnt = g_counts[s];
    int c0 = threadIdx.x;
    int c1 = c0 + DIM;
    float a0 = 0.f, a1 = 0.f;
    for (int i = 0; i < cnt; i++) {
        const float* row = path_feats + (size_t)g_edge_list[beg + i] * EDIM;
        a0 += fmaxf(row[c0], 0.f);
        if (c1 < EDIM) a1 += fmaxf(row[c1], 0.f);
    }
    g_agg[(size_t)s * EDIM + c0] = a0;
    if (c1 < EDIM) g_agg[(size_t)s * EDIM + c1] = a1;
}

// ----------------------------------------------------------------------------
// Generic tiled fp32 SGEMM for node phase, N fixed = 128, B row-major [K,128].
// Batched over blockIdx.y via element offsets.
// ----------------------------------------------------------------------------
template <int BM, int TM>
__global__ __launch_bounds__(256)
void sgemm_k(const float* __restrict__ A, int lda, size_t aOff,
             const float* __restrict__ B, size_t bOff,
             float* __restrict__ C, int ldc, size_t cOff,
             int M, int K,
             const float* __restrict__ bias, int biasOff,
             const float* __restrict__ addmat, int ld_add,
             const int* __restrict__ gather_idx,
             int do_relu)
{
    constexpr int BN = 128, BK = 16, TN = 8;
    __shared__ float As[BK][BM];
    __shared__ float Bs[BK][BN];

    int yb = blockIdx.y;
    A += (size_t)yb * aOff;
    B += (size_t)yb * bOff;
    C += (size_t)yb * cOff;
    if (bias) bias += (size_t)yb * biasOff;

    int m0 = blockIdx.x * BM;
    int tid = threadIdx.x;
    int trow = tid / 16;
    int tcol = tid % 16;

    float acc[TM][TN];
    #pragma unroll
    for (int i = 0; i < TM; i++)
        #pragma unroll
        for (int j = 0; j < TN; j++) acc[i][j] = 0.f;

    int ntiles = (K + BK - 1) / BK;
    for (int t = 0; t < ntiles; t++) {
        int k0 = t * BK;
        constexpr int A4 = (BM * BK / 4) / 256;
        #pragma unroll
        for (int r = 0; r < A4; r++) {
            int idx = tid + r * 256;
            int m = idx / 4;
            int kq = (idx % 4) * 4;
            float4 v = make_float4(0.f, 0.f, 0.f, 0.f);
            int gm = m0 + m;
            if (gm < M) {
                int k = k0 + kq;
                if (k + 3 < K) {
                    v = *(const float4*)(A + (size_t)gm * lda + k);
                } else {
                    float tmp[4] = {0.f, 0.f, 0.f, 0.f};
                    #pragma unroll
                    for (int q = 0; q < 4; q++)
                        if (k + q < K) tmp[q] = A[(size_t)gm * lda + k + q];
                    v = make_float4(tmp[0], tmp[1], tmp[2], tmp[3]);
                }
            }
            As[kq + 0][m] = v.x;
            As[kq + 1][m] = v.y;
            As[kq + 2][m] = v.z;
            As[kq + 3][m] = v.w;
        }
        #pragma unroll
        for (int r = 0; r < 2; r++) {
            int idx = tid + r * 256;
            int k = idx / 32;
            int n = (idx % 32) * 4;
            float4 v = make_float4(0.f, 0.f, 0.f, 0.f);
            if (k0 + k < K) v = *(const float4*)(B + (size_t)(k0 + k) * BN + n);
            *(float4*)&Bs[k][n] = v;
        }
        __syncthreads();

        #pragma unroll
        for (int kk = 0; kk < BK; kk++) {
            float a[TM], b[TN];
            #pragma unroll
            for (int i = 0; i < TM; i++) a[i] = As[kk][trow * TM + i];
            #pragma unroll
            for (int j = 0; j < TN; j++) b[j] = Bs[kk][tcol * TN + j];
            #pragma unroll
            for (int i = 0; i < TM; i++)
                #pragma unroll
                for (int j = 0; j < TN; j++)
                    acc[i][j] = fmaf(a[i], b[j], acc[i][j]);
        }
        __syncthreads();
    }

    #pragma unroll
    for (int i = 0; i < TM; i++) {
        int gm = m0 + trow * TM + i;
        if (gm >= M) continue;
        int arow = gather_idx ? gather_idx[gm] : gm;
        #pragma unroll
        for (int j = 0; j < TN; j++) {
            int gn = tcol * TN + j;
            float v = acc[i][j];
            if (bias)   v += bias[gn];
            if (addmat) v += addmat[(size_t)arow * ld_add + gn];
            if (do_relu) v = fmaxf(v, 0.f);
            C[(size_t)gm * ldc + gn] = v;
        }
    }
}

// ----------------------------------------------------------------------------
// tf32 tensor-core GEMM for the edge phase:
//   he[e] = path_feats[e] @ pe_tgt_W + ns[src_e] + bias_pe      (M=320000)
// BM=128, BN=128 (full), BK=16, 8 warps (2x4), warp tile 64x32, m16n8k8.
// ----------------------------------------------------------------------------
__device__ __forceinline__ uint32_t f2tf32(float x) {
    uint32_t r;
    asm("cvt.rna.tf32.f32 %0, %1;" : "=r"(r) : "f"(x));
    return r;
}

__device__ __forceinline__ void mma_tf32(float* c, const uint32_t* a, const uint32_t* b) {
    asm volatile(
        "mma.sync.aligned.m16n8k8.row.col.f32.tf32.tf32.f32 "
        "{%0,%1,%2,%3}, {%4,%5,%6,%7}, {%8,%9}, {%0,%1,%2,%3};"
        : "+f"(c[0]), "+f"(c[1]), "+f"(c[2]), "+f"(c[3])
        : "r"(a[0]), "r"(a[1]), "r"(a[2]), "r"(a[3]), "r"(b[0]), "r"(b[1]));
}

__global__ __launch_bounds__(256)
void edge_gemm_tf32(const float* __restrict__ A,   // path_feats [NEDGE][EDIM]
                    const float* __restrict__ B,   // pe_tgt_W [EDIM][128]
                    const int* __restrict__ src,
                    const float* __restrict__ nsm, // g_ns [NSRC][128]
                    float* __restrict__ C)         // g_he [NEDGE][128]
{
    constexpr int BM = 128, BK = 16;
    constexpr int AS = 20;   // smem stride for A rows (conflict-free frag loads)
    constexpr int BS = 136;  // smem stride for B rows (conflict-free frag loads)
    __shared__ uint32_t sA[BM * AS];
    __shared__ uint32_t sB[BK * BS];
    __shared__ float sbias[128];

    int tid = threadIdx.x;
    int lane = tid & 31, warp = tid >> 5;
    int g = lane >> 2, t = lane & 3;
    int wm = warp >> 2, wn = warp & 3;   // wm 0..1 (64 rows), wn 0..3 (32 cols)
    int m0blk = blockIdx.x * BM;

    if (tid < 128) sbias[tid] = g_bias_pe[tid];

    float acc[4][4][4];
    #pragma unroll
    for (int mf = 0; mf < 4; mf++)
        #pragma unroll
        for (int nf = 0; nf < 4; nf++)
            #pragma unroll
            for (int q = 0; q < 4; q++) acc[mf][nf][q] = 0.f;

    for (int k0 = 0; k0 < EDIM; k0 += BK) {
        // stage A tile: 128 rows x 16 k (512 float4 / 256 threads = 2 each)
        #pragma unroll
        for (int r = 0; r < 2; r++) {
            int idx = tid + r * 256;
            int m = idx >> 2;
            int kq = (idx & 3) * 4;
            int k = k0 + kq;
            float4 v;
            if (k + 3 < EDIM) {
                v = *(const float4*)(A + (size_t)(m0blk + m) * EDIM + k);
            } else {
                v.x = (k + 0 < EDIM) ? A[(size_t)(m0blk + m) * EDIM + k + 0] : 0.f;
                v.y = (k + 1 < EDIM) ? A[(size_t)(m0blk + m) * EDIM + k + 1] : 0.f;
                v.z = (k + 2 < EDIM) ? A[(size_t)(m0blk + m) * EDIM + k + 2] : 0.f;
                v.w = (k + 3 < EDIM) ? A[(size_t)(m0blk + m) * EDIM + k + 3] : 0.f;
            }
            uint32_t* p = sA + m * AS + kq;
            p[0] = f2tf32(v.x); p[1] = f2tf32(v.y);
            p[2] = f2tf32(v.z); p[3] = f2tf32(v.w);
        }
        // stage B tile: 16 k-rows x 128 n
        #pragma unroll
        for (int r = 0; r < 2; r++) {
            int idx = tid + r * 256;
            int k = idx >> 5;
            int n = (idx & 31) * 4;
            float4 v = make_float4(0.f, 0.f, 0.f, 0.f);
            if (k0 + k < EDIM) v = *(const float4*)(B + (size_t)(k0 + k) * 128 + n);
            uint32_t* p = sB + k * BS + n;
            p[0] = f2tf32(v.x); p[1] = f2tf32(v.y);
            p[2] = f2tf32(v.z); p[3] = f2tf32(v.w);
        }
        __syncthreads();

        #pragma unroll
        for (int kk = 0; kk < BK; kk += 8) {
            uint32_t bf[4][2];
            #pragma unroll
            for (int nf = 0; nf < 4; nf++) {
                int n = wn * 32 + nf * 8 + g;
                bf[nf][0] = sB[(kk + t) * BS + n];
                bf[nf][1] = sB[(kk + t + 4) * BS + n];
            }
            #pragma unroll
            for (int mf = 0; mf < 4; mf++) {
                int m = wm * 64 + mf * 16 + g;
                uint32_t af[4];
                af[0] = sA[m * AS + kk + t];
                af[1] = sA[(m + 8) * AS + kk + t];
                af[2] = sA[m * AS + kk + t + 4];
                af[3] = sA[(m + 8) * AS + kk + t + 4];
                #pragma unroll
                for (int nf = 0; nf < 4; nf++)
                    mma_tf32(acc[mf][nf], af, bf[nf]);
            }
        }
        __syncthreads();
    }

    // epilogue: + bias + ns[src]  (M is exact multiple of 128, no guards)
    #pragma unroll
    for (int mf = 0; mf < 4; mf++) {
        int r0 = m0blk + wm * 64 + mf * 16 + g;
        int r1 = r0 + 8;
        int s0 = src[r0], s1 = src[r1];
        #pragma unroll
        for (int nf = 0; nf < 4; nf++) {
            int n = wn * 32 + nf * 8 + t * 2;
            float2 ns0 = *(const float2*)(nsm + (size_t)s0 * 128 + n);
            float2 ns1 = *(const float2*)(nsm + (size_t)s1 * 128 + n);
            float2 v0, v1;
            v0.x = acc[mf][nf][0] + sbias[n]     + ns0.x;
            v0.y = acc[mf][nf][1] + sbias[n + 1] + ns0.y;
            v1.x = acc[mf][nf][2] + sbias[n]     + ns1.x;
            v1.y = acc[mf][nf][3] + sbias[n + 1] + ns1.y;
            *(float2*)(C + (size_t)r0 * 128 + n) = v0;
            *(float2*)(C + (size_t)r1 * 128 + n) = v1;
        }
    }
}

// ----------------------------------------------------------------------------
// Column stats (sum, sumsq) of an [M x 128] matrix; batched via blockIdx.y
// ----------------------------------------------------------------------------
__global__ void colstats_kernel(const float* __restrict__ X, int M,
                                float* __restrict__ S, float* __restrict__ Q,
                                size_t xOff)
{
    int yb = blockIdx.y;
    X += (size_t)yb * xOff;
    S += yb * DIM;
    Q += yb * DIM;
    int c = threadIdx.x;
    float s = 0.f, q = 0.f;
    for (int r = blockIdx.x; r < M; r += gridDim.x) {
        float v = X[(size_t)r * DIM + c];
        s += v;
        q += v * v;
    }
    atomicAdd(&S[c], s);
    atomicAdd(&Q[c], q);
}

// batched z = relu(BN(y)) over the 3 convs
__global__ void bnrelu3_kernel(const float* __restrict__ X, float* __restrict__ Z,
                               const float* __restrict__ S, const float* __restrict__ Q,
                               const float* __restrict__ g, const float* __restrict__ b)
{
    int yb = blockIdx.y;
    X += (size_t)yb * NSRC * DIM;
    Z += (size_t)yb * NSRC * DIM;
    S += yb * DIM; Q += yb * DIM; g += yb * DIM; b += yb * DIM;
    int i = blockIdx.x * blockDim.x + threadIdx.x;
    if (i >= NSRC * DIM) return;
    int c = i & (DIM - 1);
    float mean = S[c] * (1.0f / NSRC);
    float var = Q[c] * (1.0f / NSRC) - mean * mean;
    float v = (X[i] - mean) * rsqrtf(var + 1e-5f) * g[c] + b[c];
    Z[i] = fmaxf(v, 0.f);
}

__global__ void combine_bias_kernel(const float* __restrict__ b1,
                                    const float* __restrict__ b2)
{
    int c = threadIdx.x;
    g_bias_pe[c] = b1[c] + b2[c];
}

__global__ void edge_params_kernel(const float* __restrict__ g,
                                   const float* __restrict__ b)
{
    int c = threadIdx.x;
    const float invE = 1.0f / (float)NEDGE;
    float mean = g_ESQ[c] * invE;
    float var = g_ESQ[DIM + c] * invE - mean * mean;
    float a = g[c] * rsqrtf(var + 1e-5f);
    g_alpha[c] = a;
    g_beta[c] = b[c] - mean * a;
}

// scores[e] = sum_j relu(alpha_j*h[e][j] + beta_j) * w_j   (warp per edge)
__global__ void score_kernel(const float* __restrict__ w)
{
    __shared__ float sa[DIM], sb[DIM], sw[DIM];
    int tid = threadIdx.x;
    if (tid < DIM) { sa[tid] = g_alpha[tid]; sb[tid] = g_beta[tid]; sw[tid] = w[tid]; }
    __syncthreads();
    int warp = tid >> 5, lane = tid & 31;
    int nw = blockDim.x >> 5;
    for (int e = blockIdx.x * nw + warp; e < NEDGE; e += gridDim.x * nw) {
        const float* row = g_he + (size_t)e * DIM;
        float s = 0.f;
        #pragma unroll
        for (int j0 = 0; j0 < DIM; j0 += 32) {
            int j = j0 + lane;
            s += fmaxf(fmaf(sa[j], row[j], sb[j]), 0.f) * sw[j];
        }
        #pragma unroll
        for (int o = 16; o; o >>= 1) s += __shfl_down_sync(0xffffffffu, s, o);
        if (lane == 0) g_scores[e] = s;
    }
}

// ----------------------------------------------------------------------------
// Top-6
// ----------------------------------------------------------------------------
__global__ void topk_block_kernel()
{
    const int CHUNK = 1280;
    __shared__ float sv[CHUNK];
    __shared__ float rv[256];
    __shared__ int   ri[256];
    int tid = threadIdx.x;
    int base = blockIdx.x * CHUNK;
    for (int i = tid; i < CHUNK; i += 256) sv[i] = g_scores[base + i];
    __syncthreads();
    for (int r = 0; r < TOPN; r++) {
        float best = -CUDART_INF_F;
        int bi = 0x7fffffff;
        for (int i = tid; i < CHUNK; i += 256) {
            float v = sv[i];
            int gi = base + i;
            if (v > best || (v == best && gi < bi)) { best = v; bi = gi; }
        }
        rv[tid] = best; ri[tid] = bi;
        __syncthreads();
        for (int off = 128; off; off >>= 1) {
            if (tid < off) {
                float v2 = rv[tid + off]; int i2 = ri[tid + off];
                if (v2 > rv[tid] || (v2 == rv[tid] && i2 < ri[tid])) { rv[tid] = v2; ri[tid] = i2; }
            }
            __syncthreads();
        }
        if (tid == 0) {
            g_cvals[blockIdx.x * TOPN + r] = rv[0];
            g_cidx[blockIdx.x * TOPN + r] = ri[0];
            sv[ri[0] - base] = -CUDART_INF_F;
        }
        __syncthreads();
    }
}

__global__ void topk_final_kernel(float* __restrict__ out)
{
    const int NC = NCAND_BLOCKS * TOPN;
    __shared__ float sv[NC];
    __shared__ int   si[NC];
    __shared__ float rv[256];
    __shared__ int   rgi[256];
    __shared__ int   rslot[256];
    int tid = threadIdx.x;
    for (int i = tid; i < NC; i += 256) { sv[i] = g_cvals[i]; si[i] = g_cidx[i]; }
    __syncthreads();
    for (int r = 0; r < TOPN; r++) {
        float best = -CUDART_INF_F;
        int bi = 0x7fffffff;
        int bslot = -1;
        for (int i = tid; i < NC; i += 256) {
            float v = sv[i];
            int gi = si[i];
            if (v > best || (v == best && gi < bi)) { best = v; bi = gi; bslot = i; }
        }
        rv[tid] = best; rgi[tid] = bi; rslot[tid] = bslot;
        __syncthreads();
        for (int off = 128; off; off >>= 1) {
            if (tid < off) {
                float v2 = rv[tid + off]; int i2 = rgi[tid + off]; int s2 = rslot[tid + off];
                if (v2 > rv[tid] || (v2 == rv[tid] && i2 < rgi[tid])) {
                    rv[tid] = v2; rgi[tid] = i2; rslot[tid] = s2;
                }
            }
            __syncthreads();
        }
        if (tid == 0) {
            out[(size_t)NSRC * DIM + r] = rv[0];
            out[(size_t)NSRC * DIM + TOPN + r] = (float)rgi[0];
            if (rslot[0] >= 0) sv[rslot[0]] = -CUDART_INF_F;
        }
        __syncthreads();
    }
}

// ----------------------------------------------------------------------------
// Launch
// ----------------------------------------------------------------------------
extern "C" void kernel_launch(void* const* d_in, const int* in_sizes, int n_in,
                              void* d_out, int out_size)
{
    (void)in_sizes; (void)n_in; (void)out_size;
    const float* paths_srcs  = (const float*)d_in[0];
    const float* path_feats  = (const float*)d_in[1];
    const int*   src_ids     = (const int*)  d_in[2];
    const float* conv_edge_W = (const float*)d_in[3];
    const float* conv_edge_b = (const float*)d_in[4];
    const float* conv_W1     = (const float*)d_in[5];
    const float* conv_bn_g   = (const float*)d_in[6];
    const float* conv_bn_b   = (const float*)d_in[7];
    const float* conv_W2     = (const float*)d_in[8];
    const float* lin1_W      = (const float*)d_in[9];
    const float* lin1_b      = (const float*)d_in[10];
    const float* lin2_W      = (const float*)d_in[11];
    const float* lin2_b      = (const float*)d_in[12];
    const float* pe_src_W    = (const float*)d_in[13];
    const float* pe_src_b    = (const float*)d_in[14];
    const float* pe_tgt_W    = (const float*)d_in[15];
    const float* pe_tgt_b    = (const float*)d_in[16];
    const float* pe_bn_g     = (const float*)d_in[17];
    const float* pe_bn_b     = (const float*)d_in[18];
    const float* score_w     = (const float*)d_in[19];
    float* out = (float*)d_out;

    void *p_counts, *p_cursor, *p_SQ, *p_ESQ;
    cudaGetSymbolAddress(&p_counts, g_counts);
    cudaGetSymbolAddress(&p_cursor, g_cursor);
    cudaGetSymbolAddress(&p_SQ, g_SQ);
    cudaGetSymbolAddress(&p_ESQ, g_ESQ);
    float *agg, *H, *y, *z, *H2, *u, *ns, *he;
    cudaGetSymbolAddress((void**)&agg, g_agg);
    cudaGetSymbolAddress((void**)&H, g_H);
    cudaGetSymbolAddress((void**)&y, g_y);
    cudaGetSymbolAddress((void**)&z, g_z);
    cudaGetSymbolAddress((void**)&H2, g_H2);
    cudaGetSymbolAddress((void**)&u, g_u);
    cudaGetSymbolAddress((void**)&ns, g_ns);
    cudaGetSymbolAddress((void**)&he, g_he);
    float* S = (float*)p_SQ;
    float* Q = S + 3 * DIM;
    float* ES = (float*)p_ESQ;
    float* EQ = ES + DIM;

    cudaMemsetAsync(p_counts, 0, NSRC * sizeof(int));
    cudaMemsetAsync(p_cursor, 0, NSRC * sizeof(int));
    cudaMemsetAsync(p_SQ, 0, 2 * 3 * DIM * sizeof(float));
    cudaMemsetAsync(p_ESQ, 0, 2 * DIM * sizeof(float));

    // CSR build + aggregation
    count_kernel<<<(NEDGE + 255) / 256, 256>>>(src_ids);
    scan_kernel<<<1, 1024>>>();
    scatter_kernel<<<(NEDGE + 255) / 256, 256>>>(src_ids);
    agg_kernel<<<NSRC, DIM>>>(path_feats);

    const int NODE_GRID = (NSRC + 63) / 64;   // 157
    dim3 gN3(NODE_GRID, 3);

    // h_i = paths_srcs + agg @ edgeW_i + b_i   (batched over 3 convs)
    sgemm_k<64, 4><<<gN3, 256>>>(
        agg, EDIM, 0,
        conv_edge_W, (size_t)EDIM * DIM,
        H, 3 * DIM, DIM,
        NSRC, EDIM,
        conv_edge_b, DIM, paths_srcs, DIM, nullptr, 0);

    // y_i = h_i @ W1_i (batched)
    sgemm_k<64, 4><<<gN3, 256>>>(
        H, 3 * DIM, DIM,
        conv_W1, (size_t)DIM * DIM,
        y, DIM, (size_t)NSRC * DIM,
        NSRC, DIM,
        nullptr, 0, nullptr, 0, nullptr, 0);

    colstats_kernel<<<dim3(256, 3), DIM>>>(y, NSRC, S, Q, (size_t)NSRC * DIM);
    bnrelu3_kernel<<<dim3((NSRC * DIM + 255) / 256, 3), 256>>>(
        y, z, S, Q, conv_bn_g, conv_bn_b);

    // hs_i = z_i @ W2_i (batched, into H2 concat columns)
    sgemm_k<64, 4><<<gN3, 256>>>(
        z, DIM, (size_t)NSRC * DIM,
        conv_W2, (size_t)DIM * DIM,
        H2, 3 * DIM, DIM,
        NSRC, DIM,
        nullptr, 0, nullptr, 0, nullptr, 0);

    // u = relu(H2 @ lin1 + b1) ; node_emb = u @ lin2 + b2 (into d_out)
    sgemm_k<64, 4><<<NODE_GRID, 256>>>(
        H2, 3 * DIM, 0, lin1_W, 0, u, DIM, 0,
        NSRC, 3 * DIM, lin1_b, 0, nullptr, 0, nullptr, 1);
    sgemm_k<64, 4><<<NODE_GRID, 256>>>(
        u, DIM, 0, lin2_W, 0, out, DIM, 0,
        NSRC, DIM, lin2_b, 0, nullptr, 0, nullptr, 0);
    // ns = node_emb @ pe_src_W
    sgemm_k<64, 4><<<NODE_GRID, 256>>>(
        out, DIM, 0, pe_src_W, 0, ns, DIM, 0,
        NSRC, DIM, nullptr, 0, nullptr, 0, nullptr, 0);

    // edge phase: tf32 tensor-core GEMM with fused gather/bias epilogue
    combine_bias_kernel<<<1, DIM>>>(pe_src_b, pe_tgt_b);
    edge_gemm_tf32<<<NEDGE / 128, 256>>>(path_feats, pe_tgt_W, src_ids, ns, he);

    // edge BN stats -> params -> scores -> top-6
    colstats_kernel<<<dim3(2048, 1), DIM>>>(he, NEDGE, ES, EQ, 0);
    edge_params_kernel<<<1, DIM>>>(pe_bn_g, pe_bn_b);
    score_kernel<<<512, 256>>>(score_w);
    topk_block_kernel<<<NCAND_BLOCKS, 256>>>();
    topk_final_kernel<<<1, 256>>>(out);
}

// round 9
// speedup vs baseline: 1.9103x; 1.3408x over previous
#include <cuda_runtime.h>
#include <math_constants.h>
#include <cstdint>
#include <cstdio>

#define NSRC  10000
#define NEDGE 320000
#define DIM   128
#define EDIM  236
#define TOPN  6
#define NCAND_BLOCKS 250   // 250 * 1280 == 320000 exactly

// ----------------------------------------------------------------------------
// Scratch (device globals)
// ----------------------------------------------------------------------------
__device__ int   g_counts[NSRC];
__device__ int   g_cursor[NSRC];
__device__ int   g_offsets[NSRC];
__device__ int   g_edge_list[NEDGE];
__device__ float g_agg[NSRC * EDIM];
__device__ float g_H[NSRC * 3 * DIM];
__device__ float g_y[3 * NSRC * DIM];
__device__ float g_H2[NSRC * 3 * DIM];
__device__ float g_u[NSRC * DIM];
__device__ float g_ns[NSRC * DIM];
__device__ float g_SQ[2 * 3 * DIM];        // S[0:384] | Q[384:768]
__device__ float g_ESQ[2 * DIM];           // edge S | Q
__device__ float g_nalpha[3 * DIM];
__device__ float g_nbeta[3 * DIM];
__device__ float g_alpha[DIM];
__device__ float g_beta[DIM];
__device__ float g_bias_pe[DIM];
__device__ float g_Wc[2 * DIM * DIM];      // [0]=lin2_W copy, [1]=lin2_W@pe_src_W
__device__ float g_bc[2 * DIM];            // [0]=lin2_b,      [1]=lin2_b@pe_src_W
__device__ float g_he[(size_t)NEDGE * DIM];
__device__ float g_scores[NEDGE];
__device__ float g_cvals[NCAND_BLOCKS * TOPN];
__device__ int   g_cidx[NCAND_BLOCKS * TOPN];

// ----------------------------------------------------------------------------
// cp.async helpers
// ----------------------------------------------------------------------------
__device__ __forceinline__ void cp_async16(uint32_t smem_addr, const void* gptr, int src_bytes) {
    asm volatile("cp.async.cg.shared.global [%0], [%1], 16, %2;"
                 :: "r"(smem_addr), "l"(gptr), "r"(src_bytes));
}
__device__ __forceinline__ void cp_commit() {
    asm volatile("cp.async.commit_group;" ::: "memory");
}
template <int N>
__device__ __forceinline__ void cp_wait() {
    asm volatile("cp.async.wait_group %0;" :: "n"(N));
}

// ----------------------------------------------------------------------------
// CSR build
// ----------------------------------------------------------------------------
__global__ void count_kernel(const int* __restrict__ src) {
    int e = blockIdx.x * blockDim.x + threadIdx.x;
    if (e < NEDGE) atomicAdd(&g_counts[src[e]], 1);
}

__global__ void scan_kernel() {
    __shared__ int sh[1024];
    const int CH = 10;
    int tid = threadIdx.x;
    int base = tid * CH;
    int loc[CH];
    int s = 0;
    #pragma unroll
    for (int j = 0; j < CH; j++) {
        int idx = base + j;
        int v = (idx < NSRC) ? g_counts[idx] : 0;
        loc[j] = s;
        s += v;
    }
    sh[tid] = s;
    __syncthreads();
    for (int off = 1; off < 1024; off <<= 1) {
        int v = (tid >= off) ? sh[tid - off] : 0;
        __syncthreads();
        sh[tid] += v;
        __syncthreads();
    }
    int pre = (tid == 0) ? 0 : sh[tid - 1];
    #pragma unroll
    for (int j = 0; j < CH; j++) {
        int idx = base + j;
        if (idx < NSRC) g_offsets[idx] = pre + loc[j];
    }
}

__global__ void scatter_kernel(const int* __restrict__ src) {
    int e = blockIdx.x * blockDim.x + threadIdx.x;
    if (e < NEDGE) {
        int s = src[e];
        int p = g_offsets[s] + atomicAdd(&g_cursor[s], 1);
        g_edge_list[p] = e;
    }
}

__global__ void agg_kernel(const float* __restrict__ path_feats) {
    int s = blockIdx.x;
    int beg = g_offsets[s];
    int cnt = g_counts[s];
    int c0 = threadIdx.x;
    int c1 = c0 + DIM;
    float a0 = 0.f, a1 = 0.f;
    for (int i = 0; i < cnt; i++) {
        const float* row = path_feats + (size_t)g_edge_list[beg + i] * EDIM;
        a0 += fmaxf(row[c0], 0.f);
        if (c1 < EDIM) a1 += fmaxf(row[c1], 0.f);
    }
    g_agg[(size_t)s * EDIM + c0] = a0;
    if (c1 < EDIM) g_agg[(size_t)s * EDIM + c1] = a1;
}

// ----------------------------------------------------------------------------
// Node fp32 GEMM, N fixed = 128, B row-major [K,128]; batched via blockIdx.y.
// Flags: BIAS, ADDM (add addmat row), RELU, STATS (fused col sum/sumsq into
// S/Q), BNA (apply z=relu(alpha*a+beta) to A during staging).
// ----------------------------------------------------------------------------
template <int BM, int TM, bool BIAS, bool ADDM, bool RELU, bool STATS, bool BNA>
__global__ __launch_bounds__(256)
void node_gemm(const float* __restrict__ A, int lda, size_t aOff,
               const float* __restrict__ B, size_t bOff,
               float* __restrict__ C, int ldc, size_t cOff,
               float* __restrict__ Calt,
               int M, int K,
               const float* __restrict__ bias, int biasOff,
               const float* __restrict__ addmat, int ld_add,
               float* __restrict__ Sg, float* __restrict__ Qg,
               const float* __restrict__ bnAl, const float* __restrict__ bnBe)
{
    constexpr int BK = 16, TN = 8;
    __shared__ float As[BK][BM];
    __shared__ float Bs[BK][DIM];
    __shared__ float sS[DIM], sQ[DIM];

    int yb = blockIdx.y;
    A += (size_t)yb * aOff;
    B += (size_t)yb * bOff;
    if (Calt && yb == 1) C = Calt; else C += (size_t)yb * cOff;
    if (BIAS) bias += (size_t)yb * biasOff;
    const float* al = nullptr; const float* be = nullptr;
    if (BNA) { al = bnAl + yb * DIM; be = bnBe + yb * DIM; }
    if (STATS) { Sg += yb * DIM; Qg += yb * DIM; }

    int m0 = blockIdx.x * BM;
    int tid = threadIdx.x;
    int trow = tid / 16;
    int tcol = tid % 16;

    if (STATS && tid < DIM) { sS[tid] = 0.f; sQ[tid] = 0.f; }

    float acc[TM][TN];
    #pragma unroll
    for (int i = 0; i < TM; i++)
        #pragma unroll
        for (int j = 0; j < TN; j++) acc[i][j] = 0.f;

    int ntiles = (K + BK - 1) / BK;
    for (int t = 0; t < ntiles; t++) {
        int k0 = t * BK;
        constexpr int A4 = (BM * BK / 4) / 256;   // 2 for BM=128, 1 for BM=64
        #pragma unroll
        for (int r = 0; r < A4; r++) {
            int idx = tid + r * 256;
            int m = idx / 4;
            int kq = (idx % 4) * 4;
            float4 v = make_float4(0.f, 0.f, 0.f, 0.f);
            int gm = m0 + m;
            int k = k0 + kq;
            if (gm < M) {
                if (k + 3 < K) {
                    v = *(const float4*)(A + (size_t)gm * lda + k);
                    if (BNA) {
                        v.x = fmaxf(fmaf(al[k + 0], v.x, be[k + 0]), 0.f);
                        v.y = fmaxf(fmaf(al[k + 1], v.y, be[k + 1]), 0.f);
                        v.z = fmaxf(fmaf(al[k + 2], v.z, be[k + 2]), 0.f);
                        v.w = fmaxf(fmaf(al[k + 3], v.w, be[k + 3]), 0.f);
                    }
                } else {
                    float tmp[4] = {0.f, 0.f, 0.f, 0.f};
                    #pragma unroll
                    for (int q = 0; q < 4; q++)
                        if (k + q < K) {
                            float x = A[(size_t)gm * lda + k + q];
                            if (BNA) x = fmaxf(fmaf(al[k + q], x, be[k + q]), 0.f);
                            tmp[q] = x;
                        }
                    v = make_float4(tmp[0], tmp[1], tmp[2], tmp[3]);
                }
            }
            As[kq + 0][m] = v.x;
            As[kq + 1][m] = v.y;
            As[kq + 2][m] = v.z;
            As[kq + 3][m] = v.w;
        }
        #pragma unroll
        for (int r = 0; r < 2; r++) {
            int idx = tid + r * 256;
            int k = idx / 32;
            int n = (idx % 32) * 4;
            float4 v = make_float4(0.f, 0.f, 0.f, 0.f);
            if (k0 + k < K) v = *(const float4*)(B + (size_t)(k0 + k) * DIM + n);
            *(float4*)&Bs[k][n] = v;
        }
        __syncthreads();

        #pragma unroll
        for (int kk = 0; kk < BK; kk++) {
            float a[TM], b[TN];
            #pragma unroll
            for (int i = 0; i < TM; i++) a[i] = As[kk][trow * TM + i];
            #pragma unroll
            for (int j = 0; j < TN; j++) b[j] = Bs[kk][tcol * TN + j];
            #pragma unroll
            for (int i = 0; i < TM; i++)
                #pragma unroll
                for (int j = 0; j < TN; j++)
                    acc[i][j] = fmaf(a[i], b[j], acc[i][j]);
        }
        __syncthreads();
    }

    float cs[TN], cq[TN];
    #pragma unroll
    for (int j = 0; j < TN; j++) { cs[j] = 0.f; cq[j] = 0.f; }

    #pragma unroll
    for (int i = 0; i < TM; i++) {
        int gm = m0 + trow * TM + i;
        if (gm >= M) continue;
        #pragma unroll
        for (int j = 0; j < TN; j++) {
            int gn = tcol * TN + j;
            float v = acc[i][j];
            if (BIAS) v += bias[gn];
            if (ADDM) v += addmat[(size_t)gm * ld_add + gn];
            if (RELU) v = fmaxf(v, 0.f);
            if (STATS) { cs[j] += v; cq[j] += v * v; }
            C[(size_t)gm * ldc + gn] = v;
        }
    }
    if (STATS) {
        #pragma unroll
        for (int j = 0; j < TN; j++) {
            int gn = tcol * TN + j;
            atomicAdd(&sS[gn], cs[j]);
            atomicAdd(&sQ[gn], cq[j]);
        }
        __syncthreads();
        if (tid < DIM) {
            atomicAdd(&Sg[tid], sS[tid]);
            atomicAdd(&Qg[tid], sQ[tid]);
        }
    }
}

// ----------------------------------------------------------------------------
// W' = lin2_W @ pe_src_W, b' = lin2_b @ pe_src_W; also copy lin2 into slot 0.
// grid 128 blocks (k), 128 threads (n)
// ----------------------------------------------------------------------------
__global__ void wcomb_kernel(const float* __restrict__ lin2W,
                             const float* __restrict__ lin2b,
                             const float* __restrict__ peW)
{
    int k = blockIdx.x, n = threadIdx.x;
    float s = 0.f;
    for (int j = 0; j < DIM; j++)
        s = fmaf(lin2W[k * DIM + j], peW[j * DIM + n], s);
    g_Wc[DIM * DIM + k * DIM + n] = s;
    g_Wc[k * DIM + n] = lin2W[k * DIM + n];
    if (k == 0) {
        float t = 0.f;
        for (int j = 0; j < DIM; j++)
            t = fmaf(lin2b[j], peW[j * DIM + n], t);
        g_bc[DIM + n] = t;
        g_bc[n] = lin2b[n];
    }
}

// node BN params (3*128) + combined pe bias (128). 384 threads.
__global__ void params_kernel(const float* __restrict__ g, const float* __restrict__ b,
                              const float* __restrict__ pb1, const float* __restrict__ pb2)
{
    int i = threadIdx.x;
    float mean = g_SQ[i] * (1.0f / NSRC);
    float var = g_SQ[3 * DIM + i] * (1.0f / NSRC) - mean * mean;
    float a = g[i] * rsqrtf(var + 1e-5f);
    g_nalpha[i] = a;
    g_nbeta[i] = b[i] - mean * a;
    if (i < DIM) g_bias_pe[i] = pb1[i] + pb2[i];
}

// ----------------------------------------------------------------------------
// Edge GEMM: tf32 mma (raw fp32 bits), cp.async double-buffered, fused
// bias + ns[src] epilogue + fused column stats into g_ESQ.
// BM=128, BN=128, BK=16, 8 warps (2x4), warp tile 64x32, m16n8k8.
// ----------------------------------------------------------------------------
__device__ __forceinline__ void mma_tf32(float* c, const uint32_t* a, const uint32_t* b) {
    asm volatile(
        "mma.sync.aligned.m16n8k8.row.col.f32.tf32.tf32.f32 "
        "{%0,%1,%2,%3}, {%4,%5,%6,%7}, {%8,%9}, {%0,%1,%2,%3};"
        : "+f"(c[0]), "+f"(c[1]), "+f"(c[2]), "+f"(c[3])
        : "r"(a[0]), "r"(a[1]), "r"(a[2]), "r"(a[3]), "r"(b[0]), "r"(b[1]));
}

__global__ __launch_bounds__(256)
void edge_gemm_tf32(const float* __restrict__ A,   // path_feats [NEDGE][EDIM]
                    const float* __restrict__ B,   // pe_tgt_W [EDIM][128]
                    const int* __restrict__ src,
                    const float* __restrict__ nsm, // g_ns
                    float* __restrict__ C)         // g_he
{
    constexpr int BK = 16;
    constexpr int AS = 20;
    constexpr int BS = 136;
    constexpr int NT = (EDIM + BK - 1) / BK;   // 15
    __shared__ uint32_t sA[2][128 * AS];
    __shared__ uint32_t sB[2][BK * BS];
    __shared__ float sbias[DIM];
    __shared__ float sS[DIM], sQ[DIM];

    int tid = threadIdx.x;
    int lane = tid & 31, warp = tid >> 5;
    int gq = lane >> 2, tq = lane & 3;
    int wm = warp >> 2, wn = warp & 3;
    int m0blk = blockIdx.x * 128;

    if (tid < DIM) { sbias[tid] = g_bias_pe[tid]; sS[tid] = 0.f; sQ[tid] = 0.f; }

    float acc[4][4][4];
    #pragma unroll
    for (int mf = 0; mf < 4; mf++)
        #pragma unroll
        for (int nf = 0; nf < 4; nf++)
            #pragma unroll
            for (int q = 0; q < 4; q++) acc[mf][nf][q] = 0.f;

    // stage tile into buffer bi
    auto stage = [&](int t, int bi) {
        int k0 = t * BK;
        #pragma unroll
        for (int r = 0; r < 2; r++) {
            int idx = tid + r * 256;
            int m = idx >> 2;
            int kq = (idx & 3) * 4;
            int k = k0 + kq;
            const float* gp = (k < EDIM) ? (A + (size_t)(m0blk + m) * EDIM + k) : A;
            int sz = (k < EDIM) ? 16 : 0;
            uint32_t da = (uint32_t)__cvta_generic_to_shared(&sA[bi][m * AS + kq]);
            cp_async16(da, gp, sz);
        }
        #pragma unroll
        for (int r = 0; r < 2; r++) {
            int idx = tid + r * 256;
            int k = idx >> 5;
            int n = (idx & 31) * 4;
            const float* gp = (k0 + k < EDIM) ? (B + (size_t)(k0 + k) * DIM + n) : B;
            int sz = (k0 + k < EDIM) ? 16 : 0;
            uint32_t da = (uint32_t)__cvta_generic_to_shared(&sB[bi][k * BS + n]);
            cp_async16(da, gp, sz);
        }
        cp_commit();
    };

    stage(0, 0);
    for (int t = 0; t < NT; t++) {
        int bi = t & 1;
        if (t + 1 < NT) { stage(t + 1, bi ^ 1); cp_wait<1>(); }
        else            { cp_wait<0>(); }
        __syncthreads();

        const uint32_t* cA = sA[bi];
        const uint32_t* cB = sB[bi];
        #pragma unroll
        for (int kk = 0; kk < BK; kk += 8) {
            uint32_t bf[4][2];
            #pragma unroll
            for (int nf = 0; nf < 4; nf++) {
                int n = wn * 32 + nf * 8 + gq;
                bf[nf][0] = cB[(kk + tq) * BS + n];
                bf[nf][1] = cB[(kk + tq + 4) * BS + n];
            }
            #pragma unroll
            for (int mf = 0; mf < 4; mf++) {
                int m = wm * 64 + mf * 16 + gq;
                uint32_t af[4];
                af[0] = cA[m * AS + kk + tq];
                af[1] = cA[(m + 8) * AS + kk + tq];
                af[2] = cA[m * AS + kk + tq + 4];
                af[3] = cA[(m + 8) * AS + kk + tq + 4];
                #pragma unroll
                for (int nf = 0; nf < 4; nf++)
                    mma_tf32(acc[mf][nf], af, bf[nf]);
            }
        }
        __syncthreads();
    }

    // epilogue: + bias + ns[src], write, accumulate column stats
    float cs[4][2], cq[4][2];
    #pragma unroll
    for (int nf = 0; nf < 4; nf++) { cs[nf][0] = cs[nf][1] = cq[nf][0] = cq[nf][1] = 0.f; }

    #pragma unroll
    for (int mf = 0; mf < 4; mf++) {
        int r0 = m0blk + wm * 64 + mf * 16 + gq;
        int r1 = r0 + 8;
        int s0 = src[r0], s1 = src[r1];
        #pragma unroll
        for (int nf = 0; nf < 4; nf++) {
            int n = wn * 32 + nf * 8 + tq * 2;
            float2 ns0 = *(const float2*)(nsm + (size_t)s0 * DIM + n);
            float2 ns1 = *(const float2*)(nsm + (size_t)s1 * DIM + n);
            float2 v0, v1;
            v0.x = acc[mf][nf][0] + sbias[n]     + ns0.x;
            v0.y = acc[mf][nf][1] + sbias[n + 1] + ns0.y;
            v1.x = acc[mf][nf][2] + sbias[n]     + ns1.x;
            v1.y = acc[mf][nf][3] + sbias[n + 1] + ns1.y;
            *(float2*)(C + (size_t)r0 * DIM + n) = v0;
            *(float2*)(C + (size_t)r1 * DIM + n) = v1;
            cs[nf][0] += v0.x + v1.x;  cq[nf][0] += v0.x * v0.x + v1.x * v1.x;
            cs[nf][1] += v0.y + v1.y;  cq[nf][1] += v0.y * v0.y + v1.y * v1.y;
        }
    }
    #pragma unroll
    for (int nf = 0; nf < 4; nf++) {
        int n = wn * 32 + nf * 8 + tq * 2;
        atomicAdd(&sS[n], cs[nf][0]);     atomicAdd(&sQ[n], cq[nf][0]);
        atomicAdd(&sS[n + 1], cs[nf][1]); atomicAdd(&sQ[n + 1], cq[nf][1]);
    }
    __syncthreads();
    if (tid < DIM) {
        atomicAdd(&g_ESQ[tid], sS[tid]);
        atomicAdd(&g_ESQ[DIM + tid], sQ[tid]);
    }
}

__global__ void edge_params_kernel(const float* __restrict__ g,
                                   const float* __restrict__ b)
{
    int c = threadIdx.x;
    const float invE = 1.0f / (float)NEDGE;
    float mean = g_ESQ[c] * invE;
    float var = g_ESQ[DIM + c] * invE - mean * mean;
    float a = g[c] * rsqrtf(var + 1e-5f);
    g_alpha[c] = a;
    g_beta[c] = b[c] - mean * a;
}

__global__ void score_kernel(const float* __restrict__ w)
{
    __shared__ float sa[DIM], sb[DIM], sw[DIM];
    int tid = threadIdx.x;
    if (tid < DIM) { sa[tid] = g_alpha[tid]; sb[tid] = g_beta[tid]; sw[tid] = w[tid]; }
    __syncthreads();
    int warp = tid >> 5, lane = tid & 31;
    int nw = blockDim.x >> 5;
    for (int e = blockIdx.x * nw + warp; e < NEDGE; e += gridDim.x * nw) {
        const float* row = g_he + (size_t)e * DIM;
        float s = 0.f;
        #pragma unroll
        for (int j0 = 0; j0 < DIM; j0 += 32) {
            int j = j0 + lane;
            s += fmaxf(fmaf(sa[j], row[j], sb[j]), 0.f) * sw[j];
        }
        #pragma unroll
        for (int o = 16; o; o >>= 1) s += __shfl_down_sync(0xffffffffu, s, o);
        if (lane == 0) g_scores[e] = s;
    }
}

// ----------------------------------------------------------------------------
// Top-6
// ----------------------------------------------------------------------------
__global__ void topk_block_kernel()
{
    const int CHUNK = 1280;
    __shared__ float sv[CHUNK];
    __shared__ float rv[256];
    __shared__ int   ri[256];
    int tid = threadIdx.x;
    int base = blockIdx.x * CHUNK;
    for (int i = tid; i < CHUNK; i += 256) sv[i] = g_scores[base + i];
    __syncthreads();
    for (int r = 0; r < TOPN; r++) {
        float best = -CUDART_INF_F;
        int bi = 0x7fffffff;
        for (int i = tid; i < CHUNK; i += 256) {
            float v = sv[i];
            int gi = base + i;
            if (v > best || (v == best && gi < bi)) { best = v; bi = gi; }
        }
        rv[tid] = best; ri[tid] = bi;
        __syncthreads();
        for (int off = 128; off; off >>= 1) {
            if (tid < off) {
                float v2 = rv[tid + off]; int i2 = ri[tid + off];
                if (v2 > rv[tid] || (v2 == rv[tid] && i2 < ri[tid])) { rv[tid] = v2; ri[tid] = i2; }
            }
            __syncthreads();
        }
        if (tid == 0) {
            g_cvals[blockIdx.x * TOPN + r] = rv[0];
            g_cidx[blockIdx.x * TOPN + r] = ri[0];
            sv[ri[0] - base] = -CUDART_INF_F;
        }
        __syncthreads();
    }
}

__global__ void topk_final_kernel(float* __restrict__ out)
{
    const int NC = NCAND_BLOCKS * TOPN;
    __shared__ float sv[NC];
    __shared__ int   si[NC];
    __shared__ float rv[256];
    __shared__ int   rgi[256];
    __shared__ int   rslot[256];
    int tid = threadIdx.x;
    for (int i = tid; i < NC; i += 256) { sv[i] = g_cvals[i]; si[i] = g_cidx[i]; }
    __syncthreads();
    for (int r = 0; r < TOPN; r++) {
        float best = -CUDART_INF_F;
        int bi = 0x7fffffff;
        int bslot = -1;
        for (int i = tid; i < NC; i += 256) {
            float v = sv[i];
            int gi = si[i];
            if (v > best || (v == best && gi < bi)) { best = v; bi = gi; bslot = i; }
        }
        rv[tid] = best; rgi[tid] = bi; rslot[tid] = bslot;
        __syncthreads();
        for (int off = 128; off; off >>= 1) {
            if (tid < off) {
                float v2 = rv[tid + off]; int i2 = rgi[tid + off]; int s2 = rslot[tid + off];
                if (v2 > rv[tid] || (v2 == rv[tid] && i2 < rgi[tid])) {
                    rv[tid] = v2; rgi[tid] = i2; rslot[tid] = s2;
                }
            }
            __syncthreads();
        }
        if (tid == 0) {
            out[(size_t)NSRC * DIM + r] = rv[0];
            out[(size_t)NSRC * DIM + TOPN + r] = (float)rgi[0];
            if (rslot[0] >= 0) sv[rslot[0]] = -CUDART_INF_F;
        }
        __syncthreads();
    }
}

// ----------------------------------------------------------------------------
// Launch
// ----------------------------------------------------------------------------
extern "C" void kernel_launch(void* const* d_in, const int* in_sizes, int n_in,
                              void* d_out, int out_size)
{
    (void)in_sizes; (void)n_in; (void)out_size;
    const float* paths_srcs  = (const float*)d_in[0];
    const float* path_feats  = (const float*)d_in[1];
    const int*   src_ids     = (const int*)  d_in[2];
    const float* conv_edge_W = (const float*)d_in[3];
    const float* conv_edge_b = (const float*)d_in[4];
    const float* conv_W1     = (const float*)d_in[5];
    const float* conv_bn_g   = (const float*)d_in[6];
    const float* conv_bn_b   = (const float*)d_in[7];
    const float* conv_W2     = (const float*)d_in[8];
    const float* lin1_W      = (const float*)d_in[9];
    const float* lin1_b      = (const float*)d_in[10];
    const float* lin2_W      = (const float*)d_in[11];
    const float* lin2_b      = (const float*)d_in[12];
    const float* pe_src_W    = (const float*)d_in[13];
    const float* pe_src_b    = (const float*)d_in[14];
    const float* pe_tgt_W    = (const float*)d_in[15];
    const float* pe_tgt_b    = (const float*)d_in[16];
    const float* pe_bn_g     = (const float*)d_in[17];
    const float* pe_bn_b     = (const float*)d_in[18];
    const float* score_w     = (const float*)d_in[19];
    float* out = (float*)d_out;

    void *p_counts, *p_cursor, *p_SQ, *p_ESQ;
    cudaGetSymbolAddress(&p_counts, g_counts);
    cudaGetSymbolAddress(&p_cursor, g_cursor);
    cudaGetSymbolAddress(&p_SQ, g_SQ);
    cudaGetSymbolAddress(&p_ESQ, g_ESQ);
    float *agg, *H, *y, *H2, *u, *ns, *he, *Wc, *bc, *nal, *nbe;
    cudaGetSymbolAddress((void**)&agg, g_agg);
    cudaGetSymbolAddress((void**)&H, g_H);
    cudaGetSymbolAddress((void**)&y, g_y);
    cudaGetSymbolAddress((void**)&H2, g_H2);
    cudaGetSymbolAddress((void**)&u, g_u);
    cudaGetSymbolAddress((void**)&ns, g_ns);
    cudaGetSymbolAddress((void**)&he, g_he);
    cudaGetSymbolAddress((void**)&Wc, g_Wc);
    cudaGetSymbolAddress((void**)&bc, g_bc);
    cudaGetSymbolAddress((void**)&nal, g_nalpha);
    cudaGetSymbolAddress((void**)&nbe, g_nbeta);
    float* S = (float*)p_SQ;
    float* Q = S + 3 * DIM;

    cudaMemsetAsync(p_counts, 0, NSRC * sizeof(int));
    cudaMemsetAsync(p_cursor, 0, NSRC * sizeof(int));
    cudaMemsetAsync(p_SQ, 0, 2 * 3 * DIM * sizeof(float));
    cudaMemsetAsync(p_ESQ, 0, 2 * DIM * sizeof(float));

    // CSR build + aggregation
    count_kernel<<<(NEDGE + 255) / 256, 256>>>(src_ids);
    scan_kernel<<<1, 1024>>>();
    scatter_kernel<<<(NEDGE + 255) / 256, 256>>>(src_ids);
    agg_kernel<<<NSRC, DIM>>>(path_feats);

    // combined lin2/pe_src weights (independent of data; cheap)
    wcomb_kernel<<<DIM, DIM>>>(lin2_W, lin2_b, pe_src_W);

    const int G128 = (NSRC + 127) / 128;   // 79
    const int G64  = (NSRC + 63) / 64;     // 157

    // H_i = paths_srcs + agg @ edgeW_i + b_i (batched x3)
    node_gemm<128, 8, true, true, false, false, false><<<dim3(G128, 3), 256>>>(
        agg, EDIM, 0, conv_edge_W, (size_t)EDIM * DIM,
        H, 3 * DIM, DIM, nullptr, NSRC, EDIM,
        conv_edge_b, DIM, paths_srcs, DIM, nullptr, nullptr, nullptr, nullptr);

    // y_i = H_i @ W1_i (batched x3, fused column stats)
    node_gemm<128, 8, false, false, false, true, false><<<dim3(G128, 3), 256>>>(
        H, 3 * DIM, DIM, conv_W1, (size_t)DIM * DIM,
        y, DIM, (size_t)NSRC * DIM, nullptr, NSRC, DIM,
        nullptr, 0, nullptr, 0, S, Q, nullptr, nullptr);

    // BN params (node) + combined pe bias
    params_kernel<<<1, 3 * DIM>>>(conv_bn_g, conv_bn_b, pe_src_b, pe_tgt_b);

    // H2_i = relu(BN(y_i)) @ W2_i (batched x3, BN fused into A staging)
    node_gemm<128, 8, false, false, false, false, true><<<dim3(G128, 3), 256>>>(
        y, DIM, (size_t)NSRC * DIM, conv_W2, (size_t)DIM * DIM,
        H2, 3 * DIM, DIM, nullptr, NSRC, DIM,
        nullptr, 0, nullptr, 0, nullptr, nullptr, nal, nbe);

    // u = relu(H2 @ lin1 + b1)   (BM=64 for occupancy; K=384)
    node_gemm<64, 4, true, false, true, false, false><<<G64, 256>>>(
        H2, 3 * DIM, 0, lin1_W, 0, u, DIM, 0, nullptr, NSRC, 3 * DIM,
        lin1_b, 0, nullptr, 0, nullptr, nullptr, nullptr, nullptr);

    // batched: out = u@lin2+b2 ; ns = u@W' + b'  (same A)
    node_gemm<128, 8, true, false, false, false, false><<<dim3(G128, 2), 256>>>(
        u, DIM, 0, Wc, (size_t)DIM * DIM, out, DIM, 0, ns, NSRC, DIM,
        bc, DIM, nullptr, 0, nullptr, nullptr, nullptr, nullptr);

    // edge phase: tf32 tensor-core GEMM, cp.async pipelined, fused stats
    edge_gemm_tf32<<<NEDGE / 128, 256>>>(path_feats, pe_tgt_W, src_ids, ns, he);

    edge_params_kernel<<<1, DIM>>>(pe_bn_g, pe_bn_b);
    score_kernel<<<512, 256>>>(score_w);
    topk_block_kernel<<<NCAND_BLOCKS, 256>>>();
    topk_final_kernel<<<1, 256>>>(out);
}